// round 11
// baseline (speedup 1.0000x reference)
#include <cuda_runtime.h>
#include <cuda_bf16.h>
#include <cstdint>

#define NNODES 50000
#define F 128
#define EMAX 800000
#define NEG 0.2f
#define NB_SCAN ((NNODES + 1023) / 1024)   // 49

// ---------------- scratch (no allocation allowed) ----------------
__device__ int   g_deg[NNODES];
__device__ int   g_cur[NNODES];
__device__ int   g_rowstart[NNODES + 1];
__device__ int   g_bsum[64];
__device__ int   g_csr[EMAX];
__device__ int   g_is64;
__device__ float g_xl[NNODES * F];
__device__ float g_xr[NNODES * F];
__device__ float g_h[NNODES * F];

// ---------------- side stream + events (host-side only, created once) ------
static cudaStream_t g_s1 = nullptr;
static cudaEvent_t  g_ev_fork = nullptr, g_ev_join = nullptr;
namespace {
struct HxStreamInit {
    HxStreamInit() {
        cudaStreamCreateWithFlags(&g_s1, cudaStreamNonBlocking);
        cudaEventCreateWithFlags(&g_ev_fork, cudaEventDisableTiming);
        cudaEventCreateWithFlags(&g_ev_join, cudaEventDisableTiming);
    }
};
static HxStreamInit g_hx_stream_init;
}

// ---------------- zero + edge layout detection ----------------
__global__ void k_zero(const int* __restrict__ ei32) {
    int i = blockIdx.x * blockDim.x + threadIdx.x;
    if (i < NNODES) { g_deg[i] = 0; g_cur[i] = 0; }
    if (i == 0) {
        int z = 0;
#pragma unroll
        for (int k = 0; k < 8; k++) z |= ei32[2 * k + 1];
        g_is64 = (z == 0) ? 1 : 0;
    }
}

__device__ __forceinline__ int edge_val(const int* __restrict__ ei32, int idx) {
    return g_is64 ? ei32[2 * idx] : ei32[idx];
}

// ---------------- CSR construction ----------------
__global__ void k_count(const int* __restrict__ ei32, int E) {
    if (g_is64 && (E & 1) == 0) {
        int e2 = (blockIdx.x * blockDim.x + threadIdx.x) * 2;
        if (e2 >= E) return;
        int4 sv = *(const int4*)(ei32 + 2 * e2);
        int4 dv = *(const int4*)(ei32 + 2 * (E + e2));
        if (sv.x >= 0 && sv.x < NNODES && dv.x >= 0 && dv.x < NNODES)
            atomicAdd(&g_deg[dv.x], 1);
        if (sv.z >= 0 && sv.z < NNODES && dv.z >= 0 && dv.z < NNODES)
            atomicAdd(&g_deg[dv.z], 1);
    } else {
        int e = blockIdx.x * blockDim.x + threadIdx.x;
        if (e >= E) return;
        int s = edge_val(ei32, e);
        int d = edge_val(ei32, E + e);
        if (s >= 0 && s < NNODES && d >= 0 && d < NNODES) atomicAdd(&g_deg[d], 1);
    }
}

__global__ __launch_bounds__(1024) void k_scanA(int n) {
    __shared__ int wsum[32];
    int b = blockIdx.x, t = threadIdx.x;
    int lane = t & 31, w = t >> 5;
    int idx = b * 1024 + t;
    int v = (idx < n) ? g_deg[idx] : 0;
    int s = v;
#pragma unroll
    for (int o = 1; o < 32; o <<= 1) {
        int u = __shfl_up_sync(0xffffffffu, s, o);
        if (lane >= o) s += u;
    }
    if (lane == 31) wsum[w] = s;
    __syncthreads();
    if (w == 0) {
        int ws = wsum[lane];
#pragma unroll
        for (int o = 1; o < 32; o <<= 1) {
            int u = __shfl_up_sync(0xffffffffu, ws, o);
            if (lane >= o) ws += u;
        }
        wsum[lane] = ws;
    }
    __syncthreads();
    int excl = s - v + (w > 0 ? wsum[w - 1] : 0);
    if (idx < n) g_rowstart[idx] = excl;
    if (t == 1023) g_bsum[b] = wsum[31];
}

__global__ void k_scanB(int nb, int n) {
    __shared__ int s[64];
    int t = threadIdx.x;
    int v = (t < nb) ? g_bsum[t] : 0;
    s[t] = v;
    __syncthreads();
#pragma unroll
    for (int off = 1; off < 64; off <<= 1) {
        int a = (t >= off) ? s[t - off] : 0;
        __syncthreads();
        s[t] += a;
        __syncthreads();
    }
    if (t < nb) g_bsum[t] = s[t] - v;
    if (t == 63) g_rowstart[n] = s[63];
}

__global__ __launch_bounds__(1024) void k_scanC(int n) {
    int i = blockIdx.x * blockDim.x + threadIdx.x;
    if (i < n) g_rowstart[i] += g_bsum[blockIdx.x];
}

__global__ void k_fill(const int* __restrict__ ei32, int E) {
    if (g_is64 && (E & 1) == 0) {
        int e2 = (blockIdx.x * blockDim.x + threadIdx.x) * 2;
        if (e2 >= E) return;
        int4 sv = *(const int4*)(ei32 + 2 * e2);
        int4 dv = *(const int4*)(ei32 + 2 * (E + e2));
        if (sv.x >= 0 && sv.x < NNODES && dv.x >= 0 && dv.x < NNODES) {
            int pos = g_rowstart[dv.x] + atomicAdd(&g_cur[dv.x], 1);
            if (pos >= 0 && pos < EMAX) g_csr[pos] = sv.x;
        }
        if (sv.z >= 0 && sv.z < NNODES && dv.z >= 0 && dv.z < NNODES) {
            int pos = g_rowstart[dv.z] + atomicAdd(&g_cur[dv.z], 1);
            if (pos >= 0 && pos < EMAX) g_csr[pos] = sv.z;
        }
    } else {
        int e = blockIdx.x * blockDim.x + threadIdx.x;
        if (e >= E) return;
        int s = edge_val(ei32, e);
        int d = edge_val(ei32, E + e);
        if (s < 0 || s >= NNODES || d < 0 || d >= NNODES) return;
        int pos = g_rowstart[d] + atomicAdd(&g_cur[d], 1);
        if (pos >= 0 && pos < EMAX) g_csr[pos] = s;
    }
}

// ---------------- bf16 split helpers ----------------
__device__ __forceinline__ uint32_t pack_bf16x2(float lo, float hi) {
    uint32_t r;
    asm("cvt.rn.bf16x2.f32 %0, %1, %2;" : "=r"(r) : "f"(hi), "f"(lo));
    return r;
}
__device__ __forceinline__ void split_pair(float v0, float v1,
                                           uint32_t& hp, uint32_t& lp) {
    hp = pack_bf16x2(v0, v1);
    float h0 = __uint_as_float(hp << 16);
    float h1 = __uint_as_float(hp & 0xffff0000u);
    lp = pack_bf16x2(v0 - h0, v1 - h1);
}

__device__ __forceinline__ void mma_bf16(float* d, const uint32_t* a,
                                         uint32_t b0, uint32_t b1) {
    asm volatile(
        "mma.sync.aligned.m16n8k16.row.col.f32.bf16.bf16.f32 "
        "{%0,%1,%2,%3}, {%4,%5,%6,%7}, {%8,%9}, {%0,%1,%2,%3};"
        : "+f"(d[0]), "+f"(d[1]), "+f"(d[2]), "+f"(d[3])
        : "r"(a[0]), "r"(a[1]), "r"(a[2]), "r"(a[3]), "r"(b0), "r"(b1));
}

// ---------------- dual-output mma.sync GEMM ----------------
#define SSTR 12
template <int A_EXT>
__global__ __launch_bounds__(512) void k_gemm_dual(const float* __restrict__ Aext,
                                                   const float* __restrict__ Wl,
                                                   const float* __restrict__ Wr,
                                                   int nrows) {
    const float* A = A_EXT ? Aext : (const float*)g_h;

    __shared__ uint32_t As_hi[128 * SSTR];
    __shared__ uint32_t As_lo[128 * SSTR];
    __shared__ uint32_t Bs_hi[2][128 * SSTR];
    __shared__ uint32_t Bs_lo[2][128 * SSTR];

    int t    = threadIdx.x;
    int warp = t >> 5, lane = t & 31;
    int half = warp >> 3;
    int w    = warp & 7;
    int wr = (w & 3) * 32;
    int wn = (w >> 2) * 64;
    int fr = lane >> 2, fk = lane & 3;
    int row0 = blockIdx.x * 128;
    const float* W = half ? Wr : Wl;
    float*       C = half ? g_xr : g_xl;

    float acc[2][8][4];
#pragma unroll
    for (int mt = 0; mt < 2; mt++)
#pragma unroll
        for (int nt = 0; nt < 8; nt++)
#pragma unroll
            for (int q = 0; q < 4; q++) acc[mt][nt][q] = 0.f;

    for (int k0 = 0; k0 < F; k0 += 16) {
#pragma unroll
        for (int i = 0; i < 2; i++) {
            int p  = t + i * 512;
            int r  = p >> 3, kp = p & 7;
            int gr = row0 + r;
            float2 v = (gr < nrows)
                           ? *(const float2*)(A + gr * F + k0 + kp * 2)
                           : make_float2(0.f, 0.f);
            uint32_t hp, lp;
            split_pair(v.x, v.y, hp, lp);
            As_hi[r * SSTR + kp] = hp;
            As_lo[r * SSTR + kp] = lp;
        }
        {
            int ht = (t & 255);
#pragma unroll
            for (int i = 0; i < 4; i++) {
                int p = ht + i * 256;
                int n = p & 127, kp = p >> 7;
                float w0 = W[(k0 + kp * 2) * F + n];
                float w1 = W[(k0 + kp * 2 + 1) * F + n];
                uint32_t hp, lp;
                split_pair(w0, w1, hp, lp);
                Bs_hi[half][n * SSTR + kp] = hp;
                Bs_lo[half][n * SSTR + kp] = lp;
            }
        }
        __syncthreads();

        uint32_t ah[2][4], al[2][4];
#pragma unroll
        for (int mt = 0; mt < 2; mt++) {
            int rb = wr + mt * 16;
            ah[mt][0] = As_hi[(rb + fr) * SSTR + fk];
            ah[mt][1] = As_hi[(rb + fr + 8) * SSTR + fk];
            ah[mt][2] = As_hi[(rb + fr) * SSTR + fk + 4];
            ah[mt][3] = As_hi[(rb + fr + 8) * SSTR + fk + 4];
            al[mt][0] = As_lo[(rb + fr) * SSTR + fk];
            al[mt][1] = As_lo[(rb + fr + 8) * SSTR + fk];
            al[mt][2] = As_lo[(rb + fr) * SSTR + fk + 4];
            al[mt][3] = As_lo[(rb + fr + 8) * SSTR + fk + 4];
        }
#pragma unroll
        for (int nt = 0; nt < 8; nt++) {
            int nb = wn + nt * 8;
            uint32_t bh0 = Bs_hi[half][(nb + fr) * SSTR + fk];
            uint32_t bh1 = Bs_hi[half][(nb + fr) * SSTR + fk + 4];
            uint32_t bl0 = Bs_lo[half][(nb + fr) * SSTR + fk];
            uint32_t bl1 = Bs_lo[half][(nb + fr) * SSTR + fk + 4];
#pragma unroll
            for (int mt = 0; mt < 2; mt++) {
                mma_bf16(acc[mt][nt], ah[mt], bh0, bh1);
                mma_bf16(acc[mt][nt], ah[mt], bl0, bl1);
                mma_bf16(acc[mt][nt], al[mt], bh0, bh1);
            }
        }
        __syncthreads();
    }

#pragma unroll
    for (int mt = 0; mt < 2; mt++) {
#pragma unroll
        for (int nt = 0; nt < 8; nt++) {
            int col = wn + nt * 8 + fk * 2;
            int r1  = row0 + wr + mt * 16 + fr;
            int r2  = r1 + 8;
            if (r1 < nrows)
                *(float2*)(C + r1 * F + col) =
                    make_float2(acc[mt][nt][0], acc[mt][nt][1]);
            if (r2 < nrows)
                *(float2*)(C + r2 * F + col) =
                    make_float2(acc[mt][nt][2], acc[mt][nt][3]);
        }
    }
}

// ---------------- fused aggregation: TWO independent softmax chains --------
// Chain A: self-loop + even edges. Chain B: odd edges. Independent updates
// give ILP=2 on the serial exp/fma chain; merged once at the end.
template <int RW, bool RELU, int OUT_EXT>
__global__ __launch_bounds__(256) void k_agg(const float* __restrict__ att,
                                             const float* __restrict__ bias,
                                             float* __restrict__ outext) {
    const float* xl = g_xl;
    const float* xr = g_xr;
    float* out = OUT_EXT ? outext : g_h;

    int gw   = (blockIdx.x * blockDim.x + threadIdx.x) >> 5;
    int lane = threadIdx.x & 31;
    if (gw >= NNODES) return;
    int i = gw;
    int c = lane * 4;

    float4 xr4 = *(const float4*)(xr + i * F + c);
    float4 a4  = *(const float4*)(att + c);
    float4 b4  = *(const float4*)(bias + c);

    float4 xc = *(const float4*)(xl + i * F + c);   // self loop

    auto alpha_of = [&](const float4& v) -> float {
        float e0 = v.x + xr4.x; e0 = e0 > 0.f ? e0 : NEG * e0;
        float e1 = v.y + xr4.y; e1 = e1 > 0.f ? e1 : NEG * e1;
        float e2 = v.z + xr4.z; e2 = e2 > 0.f ? e2 : NEG * e2;
        float e3 = v.w + xr4.w; e3 = e3 > 0.f ? e3 : NEG * e3;
        float p = a4.x * e0 + a4.y * e1 + a4.z * e2 + a4.w * e3;
#pragma unroll
        for (int o = 1; o < RW; o <<= 1)
            p += __shfl_xor_sync(0xffffffffu, p, o);
        return p;
    };

    float  mA = alpha_of(xc), dA = 1.f;
    float4 aA = xc;
    float  mB = -1e30f, dB = 0.f;
    float4 aB = make_float4(0.f, 0.f, 0.f, 0.f);

    int beg = g_rowstart[i], end = g_rowstart[i + 1];

    // pair-wise depth-1 prefetch
    float4 c0 = make_float4(0.f, 0.f, 0.f, 0.f);
    float4 c1 = make_float4(0.f, 0.f, 0.f, 0.f);
    if (beg < end)     c0 = *(const float4*)(xl + g_csr[beg] * F + c);
    if (beg + 1 < end) c1 = *(const float4*)(xl + g_csr[beg + 1] * F + c);

    for (int e = beg; e < end; e += 2) {
        float4 v0 = c0, v1 = c1;
        bool has1 = (e + 1 < end);         // warp-uniform
        if (e + 2 < end)
            c0 = *(const float4*)(xl + g_csr[e + 2] * F + c);
        if (e + 3 < end)
            c1 = *(const float4*)(xl + g_csr[e + 3] * F + c);

        float pA = alpha_of(v0);
        float pB = alpha_of(v1);

        // chain A (always)
        {
            float mn   = fmaxf(mA, pA);
            float corr = __expf(mA - mn);
            float w    = __expf(pA - mn);
            dA = dA * corr + w;
            aA.x = aA.x * corr + w * v0.x;
            aA.y = aA.y * corr + w * v0.y;
            aA.z = aA.z * corr + w * v0.z;
            aA.w = aA.w * corr + w * v0.w;
            mA = mn;
        }
        // chain B (guarded, warp-uniform) — independent of chain A
        if (has1) {
            float mn   = fmaxf(mB, pB);
            float corr = __expf(mB - mn);
            float w    = __expf(pB - mn);
            dB = dB * corr + w;
            aB.x = aB.x * corr + w * v1.x;
            aB.y = aB.y * corr + w * v1.y;
            aB.z = aB.z * corr + w * v1.z;
            aB.w = aB.w * corr + w * v1.w;
            mB = mn;
        }
    }

    // merge chains
    float mn = fmaxf(mA, mB);
    float cA = __expf(mA - mn);
    float cB = __expf(mB - mn);
    float dsum = dA * cA + dB * cB;
    float4 acc;
    acc.x = aA.x * cA + aB.x * cB;
    acc.y = aA.y * cA + aB.y * cB;
    acc.z = aA.z * cA + aB.z * cB;
    acc.w = aA.w * cA + aB.w * cB;

    float inv = 1.0f / dsum;
    float4 o;
    o.x = acc.x * inv + b4.x;
    o.y = acc.y * inv + b4.y;
    o.z = acc.z * inv + b4.z;
    o.w = acc.w * inv + b4.w;
    if (RELU) {
        o.x = fmaxf(o.x, 0.f);
        o.y = fmaxf(o.y, 0.f);
        o.z = fmaxf(o.z, 0.f);
        o.w = fmaxf(o.w, 0.f);
    }
    *(float4*)(out + i * F + c) = o;
}

// ---------------- launch: fork gemm1 parallel to CSR chain ----------------
extern "C" void kernel_launch(void* const* d_in, const int* in_sizes, int n_in,
                              void* d_out, int out_size) {
    const float* x    = (const float*)d_in[0];
    const int*   ei32 = (const int*)d_in[1];
    const float* Wl1  = (const float*)d_in[2];
    const float* Wr1  = (const float*)d_in[3];
    const float* att1 = (const float*)d_in[4];
    const float* b1   = (const float*)d_in[5];
    const float* Wl2  = (const float*)d_in[6];
    const float* Wr2  = (const float*)d_in[7];
    const float* att2 = (const float*)d_in[8];
    const float* b2   = (const float*)d_in[9];
    float*       out  = (float*)d_out;

    int cnt = in_sizes[1];
    int E   = (cnt / 2 > EMAX) ? cnt / 4 : cnt / 2;
    if (E > EMAX) E = EMAX;

    int eb = (E + 255) / 256;
    int gb = (NNODES + 127) / 128;            // 391
    int ab = (NNODES * 32 + 255) / 256;       // 6250

    // fork: gemm1 runs on side stream, concurrent with CSR build
    cudaEventRecord(g_ev_fork, 0);
    cudaStreamWaitEvent(g_s1, g_ev_fork, 0);
    k_gemm_dual<1><<<gb, 512, 0, g_s1>>>(x, Wl1, Wr1, NNODES);
    cudaEventRecord(g_ev_join, g_s1);

    k_zero<<<(NNODES + 255) / 256, 256>>>(ei32);
    k_count<<<eb, 256>>>(ei32, E);
    k_scanA<<<NB_SCAN, 1024>>>(NNODES);
    k_scanB<<<1, 64>>>(NB_SCAN, NNODES);
    k_scanC<<<NB_SCAN, 1024>>>(NNODES);
    k_fill<<<eb, 256>>>(ei32, E);

    cudaStreamWaitEvent(0, g_ev_join, 0);
    k_agg<8, true, 0><<<ab, 256>>>(att1, b1, out);

    k_gemm_dual<0><<<gb, 512>>>(nullptr, Wl2, Wr2, NNODES);
    k_agg<32, false, 1><<<ab, 256>>>(att2, b2, out);
}

// round 12
// speedup vs baseline: 1.1333x; 1.1333x over previous
#include <cuda_runtime.h>
#include <cuda_bf16.h>
#include <cstdint>

#define NNODES 50000
#define F 128
#define EMAX 800000
#define NEG 0.2f
#define NB_SCAN ((NNODES + 1023) / 1024)   // 49

// ---------------- scratch (no allocation allowed) ----------------
__device__ int   g_deg[NNODES];
__device__ int   g_cur[NNODES];
__device__ int   g_rowstart[NNODES + 1];
__device__ int   g_bsum[64];
__device__ int   g_csr[EMAX];
__device__ int   g_is64;
__device__ float g_xl[NNODES * F];
__device__ float g_xr[NNODES * F];
__device__ float g_h[NNODES * F];

// ---------------- side stream + events (host-side only, created once) ------
static cudaStream_t g_s1 = nullptr;
static cudaEvent_t  g_ev_fork = nullptr, g_ev_join = nullptr;
namespace {
struct HxStreamInit {
    HxStreamInit() {
        cudaStreamCreateWithFlags(&g_s1, cudaStreamNonBlocking);
        cudaEventCreateWithFlags(&g_ev_fork, cudaEventDisableTiming);
        cudaEventCreateWithFlags(&g_ev_join, cudaEventDisableTiming);
    }
};
static HxStreamInit g_hx_stream_init;
}

// ---------------- zero + edge layout detection ----------------
__global__ void k_zero(const int* __restrict__ ei32) {
    int i = blockIdx.x * blockDim.x + threadIdx.x;
    if (i < NNODES) { g_deg[i] = 0; g_cur[i] = 0; }
    if (i == 0) {
        int z = 0;
#pragma unroll
        for (int k = 0; k < 8; k++) z |= ei32[2 * k + 1];
        g_is64 = (z == 0) ? 1 : 0;
    }
}

__device__ __forceinline__ int edge_val(const int* __restrict__ ei32, int idx) {
    return g_is64 ? ei32[2 * idx] : ei32[idx];
}

// ---------------- CSR construction ----------------
__global__ void k_count(const int* __restrict__ ei32, int E) {
    if (g_is64 && (E & 1) == 0) {
        int e2 = (blockIdx.x * blockDim.x + threadIdx.x) * 2;
        if (e2 >= E) return;
        int4 sv = *(const int4*)(ei32 + 2 * e2);
        int4 dv = *(const int4*)(ei32 + 2 * (E + e2));
        if (sv.x >= 0 && sv.x < NNODES && dv.x >= 0 && dv.x < NNODES)
            atomicAdd(&g_deg[dv.x], 1);
        if (sv.z >= 0 && sv.z < NNODES && dv.z >= 0 && dv.z < NNODES)
            atomicAdd(&g_deg[dv.z], 1);
    } else {
        int e = blockIdx.x * blockDim.x + threadIdx.x;
        if (e >= E) return;
        int s = edge_val(ei32, e);
        int d = edge_val(ei32, E + e);
        if (s >= 0 && s < NNODES && d >= 0 && d < NNODES) atomicAdd(&g_deg[d], 1);
    }
}

__global__ __launch_bounds__(1024) void k_scanA(int n) {
    __shared__ int wsum[32];
    int b = blockIdx.x, t = threadIdx.x;
    int lane = t & 31, w = t >> 5;
    int idx = b * 1024 + t;
    int v = (idx < n) ? g_deg[idx] : 0;
    int s = v;
#pragma unroll
    for (int o = 1; o < 32; o <<= 1) {
        int u = __shfl_up_sync(0xffffffffu, s, o);
        if (lane >= o) s += u;
    }
    if (lane == 31) wsum[w] = s;
    __syncthreads();
    if (w == 0) {
        int ws = wsum[lane];
#pragma unroll
        for (int o = 1; o < 32; o <<= 1) {
            int u = __shfl_up_sync(0xffffffffu, ws, o);
            if (lane >= o) ws += u;
        }
        wsum[lane] = ws;
    }
    __syncthreads();
    int excl = s - v + (w > 0 ? wsum[w - 1] : 0);
    if (idx < n) g_rowstart[idx] = excl;
    if (t == 1023) g_bsum[b] = wsum[31];
}

__global__ void k_scanB(int nb, int n) {
    __shared__ int s[64];
    int t = threadIdx.x;
    int v = (t < nb) ? g_bsum[t] : 0;
    s[t] = v;
    __syncthreads();
#pragma unroll
    for (int off = 1; off < 64; off <<= 1) {
        int a = (t >= off) ? s[t - off] : 0;
        __syncthreads();
        s[t] += a;
        __syncthreads();
    }
    if (t < nb) g_bsum[t] = s[t] - v;
    if (t == 63) g_rowstart[n] = s[63];
}

__global__ __launch_bounds__(1024) void k_scanC(int n) {
    int i = blockIdx.x * blockDim.x + threadIdx.x;
    if (i < n) g_rowstart[i] += g_bsum[blockIdx.x];
}

__global__ void k_fill(const int* __restrict__ ei32, int E) {
    if (g_is64 && (E & 1) == 0) {
        int e2 = (blockIdx.x * blockDim.x + threadIdx.x) * 2;
        if (e2 >= E) return;
        int4 sv = *(const int4*)(ei32 + 2 * e2);
        int4 dv = *(const int4*)(ei32 + 2 * (E + e2));
        if (sv.x >= 0 && sv.x < NNODES && dv.x >= 0 && dv.x < NNODES) {
            int pos = g_rowstart[dv.x] + atomicAdd(&g_cur[dv.x], 1);
            if (pos >= 0 && pos < EMAX) g_csr[pos] = sv.x;
        }
        if (sv.z >= 0 && sv.z < NNODES && dv.z >= 0 && dv.z < NNODES) {
            int pos = g_rowstart[dv.z] + atomicAdd(&g_cur[dv.z], 1);
            if (pos >= 0 && pos < EMAX) g_csr[pos] = sv.z;
        }
    } else {
        int e = blockIdx.x * blockDim.x + threadIdx.x;
        if (e >= E) return;
        int s = edge_val(ei32, e);
        int d = edge_val(ei32, E + e);
        if (s < 0 || s >= NNODES || d < 0 || d >= NNODES) return;
        int pos = g_rowstart[d] + atomicAdd(&g_cur[d], 1);
        if (pos >= 0 && pos < EMAX) g_csr[pos] = s;
    }
}

// ---------------- bf16 split helpers ----------------
__device__ __forceinline__ uint32_t pack_bf16x2(float lo, float hi) {
    uint32_t r;
    asm("cvt.rn.bf16x2.f32 %0, %1, %2;" : "=r"(r) : "f"(hi), "f"(lo));
    return r;
}
__device__ __forceinline__ void split_pair(float v0, float v1,
                                           uint32_t& hp, uint32_t& lp) {
    hp = pack_bf16x2(v0, v1);
    float h0 = __uint_as_float(hp << 16);
    float h1 = __uint_as_float(hp & 0xffff0000u);
    lp = pack_bf16x2(v0 - h0, v1 - h1);
}

__device__ __forceinline__ void mma_bf16(float* d, const uint32_t* a,
                                         uint32_t b0, uint32_t b1) {
    asm volatile(
        "mma.sync.aligned.m16n8k16.row.col.f32.bf16.bf16.f32 "
        "{%0,%1,%2,%3}, {%4,%5,%6,%7}, {%8,%9}, {%0,%1,%2,%3};"
        : "+f"(d[0]), "+f"(d[1]), "+f"(d[2]), "+f"(d[3])
        : "r"(a[0]), "r"(a[1]), "r"(a[2]), "r"(a[3]), "r"(b0), "r"(b1));
}

// ---------------- dual-output mma.sync GEMM ----------------
#define SSTR 12
template <int A_EXT>
__global__ __launch_bounds__(512) void k_gemm_dual(const float* __restrict__ Aext,
                                                   const float* __restrict__ Wl,
                                                   const float* __restrict__ Wr,
                                                   int nrows) {
    const float* A = A_EXT ? Aext : (const float*)g_h;

    __shared__ uint32_t As_hi[128 * SSTR];
    __shared__ uint32_t As_lo[128 * SSTR];
    __shared__ uint32_t Bs_hi[2][128 * SSTR];
    __shared__ uint32_t Bs_lo[2][128 * SSTR];

    int t    = threadIdx.x;
    int warp = t >> 5, lane = t & 31;
    int half = warp >> 3;
    int w    = warp & 7;
    int wr = (w & 3) * 32;
    int wn = (w >> 2) * 64;
    int fr = lane >> 2, fk = lane & 3;
    int row0 = blockIdx.x * 128;
    const float* W = half ? Wr : Wl;
    float*       C = half ? g_xr : g_xl;

    float acc[2][8][4];
#pragma unroll
    for (int mt = 0; mt < 2; mt++)
#pragma unroll
        for (int nt = 0; nt < 8; nt++)
#pragma unroll
            for (int q = 0; q < 4; q++) acc[mt][nt][q] = 0.f;

    for (int k0 = 0; k0 < F; k0 += 16) {
#pragma unroll
        for (int i = 0; i < 2; i++) {
            int p  = t + i * 512;
            int r  = p >> 3, kp = p & 7;
            int gr = row0 + r;
            float2 v = (gr < nrows)
                           ? *(const float2*)(A + gr * F + k0 + kp * 2)
                           : make_float2(0.f, 0.f);
            uint32_t hp, lp;
            split_pair(v.x, v.y, hp, lp);
            As_hi[r * SSTR + kp] = hp;
            As_lo[r * SSTR + kp] = lp;
        }
        {
            int ht = (t & 255);
#pragma unroll
            for (int i = 0; i < 4; i++) {
                int p = ht + i * 256;
                int n = p & 127, kp = p >> 7;
                float w0 = W[(k0 + kp * 2) * F + n];
                float w1 = W[(k0 + kp * 2 + 1) * F + n];
                uint32_t hp, lp;
                split_pair(w0, w1, hp, lp);
                Bs_hi[half][n * SSTR + kp] = hp;
                Bs_lo[half][n * SSTR + kp] = lp;
            }
        }
        __syncthreads();

        uint32_t ah[2][4], al[2][4];
#pragma unroll
        for (int mt = 0; mt < 2; mt++) {
            int rb = wr + mt * 16;
            ah[mt][0] = As_hi[(rb + fr) * SSTR + fk];
            ah[mt][1] = As_hi[(rb + fr + 8) * SSTR + fk];
            ah[mt][2] = As_hi[(rb + fr) * SSTR + fk + 4];
            ah[mt][3] = As_hi[(rb + fr + 8) * SSTR + fk + 4];
            al[mt][0] = As_lo[(rb + fr) * SSTR + fk];
            al[mt][1] = As_lo[(rb + fr + 8) * SSTR + fk];
            al[mt][2] = As_lo[(rb + fr) * SSTR + fk + 4];
            al[mt][3] = As_lo[(rb + fr + 8) * SSTR + fk + 4];
        }
#pragma unroll
        for (int nt = 0; nt < 8; nt++) {
            int nb = wn + nt * 8;
            uint32_t bh0 = Bs_hi[half][(nb + fr) * SSTR + fk];
            uint32_t bh1 = Bs_hi[half][(nb + fr) * SSTR + fk + 4];
            uint32_t bl0 = Bs_lo[half][(nb + fr) * SSTR + fk];
            uint32_t bl1 = Bs_lo[half][(nb + fr) * SSTR + fk + 4];
#pragma unroll
            for (int mt = 0; mt < 2; mt++) {
                mma_bf16(acc[mt][nt], ah[mt], bh0, bh1);
                mma_bf16(acc[mt][nt], ah[mt], bl0, bl1);
                mma_bf16(acc[mt][nt], al[mt], bh0, bh1);
            }
        }
        __syncthreads();
    }

#pragma unroll
    for (int mt = 0; mt < 2; mt++) {
#pragma unroll
        for (int nt = 0; nt < 8; nt++) {
            int col = wn + nt * 8 + fk * 2;
            int r1  = row0 + wr + mt * 16 + fr;
            int r2  = r1 + 8;
            if (r1 < nrows)
                *(float2*)(C + r1 * F + col) =
                    make_float2(acc[mt][nt][0], acc[mt][nt][1]);
            if (r2 < nrows)
                *(float2*)(C + r2 * F + col) =
                    make_float2(acc[mt][nt][2], acc[mt][nt][3]);
        }
    }
}

// ---------------- fused online-softmax aggregation (R7 form + idx-ahead) ----
template <int RW, bool RELU, int OUT_EXT>
__global__ __launch_bounds__(128) void k_agg(const float* __restrict__ att,
                                             const float* __restrict__ bias,
                                             float* __restrict__ outext) {
    const float* xl = g_xl;
    const float* xr = g_xr;
    float* out = OUT_EXT ? outext : g_h;

    int gw   = (blockIdx.x * blockDim.x + threadIdx.x) >> 5;
    int lane = threadIdx.x & 31;
    if (gw >= NNODES) return;
    int i = gw;
    int c = lane * 4;

    float4 xr4 = *(const float4*)(xr + i * F + c);
    float4 a4  = *(const float4*)(att + c);
    float4 b4  = *(const float4*)(bias + c);

    float4 xc = *(const float4*)(xl + i * F + c);   // self loop

    auto alpha_of = [&](const float4& v) -> float {
        float e0 = v.x + xr4.x; e0 = e0 > 0.f ? e0 : NEG * e0;
        float e1 = v.y + xr4.y; e1 = e1 > 0.f ? e1 : NEG * e1;
        float e2 = v.z + xr4.z; e2 = e2 > 0.f ? e2 : NEG * e2;
        float e3 = v.w + xr4.w; e3 = e3 > 0.f ? e3 : NEG * e3;
        float p = a4.x * e0 + a4.y * e1 + a4.z * e2 + a4.w * e3;
#pragma unroll
        for (int o = 1; o < RW; o <<= 1)
            p += __shfl_xor_sync(0xffffffffu, p, o);
        return p;
    };

    float  m    = alpha_of(xc);
    float  dsum = 1.f;
    float4 acc  = xc;

    int beg = g_rowstart[i], end = g_rowstart[i + 1];

    // feature prefetch depth 1 + index prefetch depth 2:
    // the feature load for e+1 issues with an ALREADY-resident index,
    // removing the idx->feature L2 serialization from the loop.
    float4 xn = make_float4(0.f, 0.f, 0.f, 0.f);
    int j1 = 0;
    if (beg < end) {
        xn = *(const float4*)(xl + g_csr[beg] * F + c);
        if (beg + 1 < end) j1 = g_csr[beg + 1];
    }
    for (int e = beg; e < end; e++) {
        float4 cur = xn;
        int jn = 0;
        if (e + 2 < end) jn = g_csr[e + 2];           // index 2 ahead
        if (e + 1 < end)
            xn = *(const float4*)(xl + j1 * F + c);   // feature 1 ahead
        j1 = jn;

        float p  = alpha_of(cur);
        float mn = fmaxf(m, p);
        float corr = __expf(m - mn);
        float w    = __expf(p - mn);
        dsum = dsum * corr + w;
        acc.x = acc.x * corr + w * cur.x;
        acc.y = acc.y * corr + w * cur.y;
        acc.z = acc.z * corr + w * cur.z;
        acc.w = acc.w * corr + w * cur.w;
        m = mn;
    }

    float inv = 1.0f / dsum;
    float4 o;
    o.x = acc.x * inv + b4.x;
    o.y = acc.y * inv + b4.y;
    o.z = acc.z * inv + b4.z;
    o.w = acc.w * inv + b4.w;
    if (RELU) {
        o.x = fmaxf(o.x, 0.f);
        o.y = fmaxf(o.y, 0.f);
        o.z = fmaxf(o.z, 0.f);
        o.w = fmaxf(o.w, 0.f);
    }
    *(float4*)(out + i * F + c) = o;
}

// ---------------- launch: fork gemm1 parallel to CSR chain ----------------
extern "C" void kernel_launch(void* const* d_in, const int* in_sizes, int n_in,
                              void* d_out, int out_size) {
    const float* x    = (const float*)d_in[0];
    const int*   ei32 = (const int*)d_in[1];
    const float* Wl1  = (const float*)d_in[2];
    const float* Wr1  = (const float*)d_in[3];
    const float* att1 = (const float*)d_in[4];
    const float* b1   = (const float*)d_in[5];
    const float* Wl2  = (const float*)d_in[6];
    const float* Wr2  = (const float*)d_in[7];
    const float* att2 = (const float*)d_in[8];
    const float* b2   = (const float*)d_in[9];
    float*       out  = (float*)d_out;

    int cnt = in_sizes[1];
    int E   = (cnt / 2 > EMAX) ? cnt / 4 : cnt / 2;
    if (E > EMAX) E = EMAX;

    int eb = (E + 255) / 256;
    int gb = (NNODES + 127) / 128;            // 391
    int ab = (NNODES * 32 + 127) / 128;       // 12500 (128-thr agg blocks)

    // fork: gemm1 runs on side stream, concurrent with CSR build
    cudaEventRecord(g_ev_fork, 0);
    cudaStreamWaitEvent(g_s1, g_ev_fork, 0);
    k_gemm_dual<1><<<gb, 512, 0, g_s1>>>(x, Wl1, Wr1, NNODES);
    cudaEventRecord(g_ev_join, g_s1);

    k_zero<<<(NNODES + 255) / 256, 256>>>(ei32);
    k_count<<<eb, 256>>>(ei32, E);
    k_scanA<<<NB_SCAN, 1024>>>(NNODES);
    k_scanB<<<1, 64>>>(NB_SCAN, NNODES);
    k_scanC<<<NB_SCAN, 1024>>>(NNODES);
    k_fill<<<eb, 256>>>(ei32, E);

    cudaStreamWaitEvent(0, g_ev_join, 0);
    k_agg<8, true, 0><<<ab, 128>>>(att1, b1, out);

    k_gemm_dual<0><<<gb, 512>>>(nullptr, Wl2, Wr2, NNODES);
    k_agg<32, false, 1><<<ab, 128>>>(att2, b2, out);
}